// round 12
// baseline (speedup 1.0000x reference)
#include <cuda_runtime.h>
#include <cuda_fp16.h>

// Problem constants
#define Bsz  2
#define Cc   64
#define Hh   128
#define Ww   256
#define HG   122880          // grid rows = L*KH
#define NPT  (HG * 3)        // total grid points (368640)
#define LOUT 40960           // output rows after stride-3 depthwise
#define TL   16              // output rows per block (dwattn)
#define NR   (3*TL + 2)      // local sampled rows incl. +/-1 halo  (50)
#define NP   (NR * 3)        // local sampled points (150)
#define VROW 36              // v_sm2 row pitch in half2 (144B)

__device__ __half g_xT[Bsz * Hh * Ww * Cc];   // x as [B,H,W,C] fp16
__device__ __half g_v[(size_t)Bsz * NPT * Cc];// sampled points [b][p][c] fp16
__device__ __half g_z[Bsz * LOUT * Cc];       // depthwise out [b*l][c] fp16

// ---------------------------------------------------------------------------
// Kernel 1: NCHW fp32 -> NHWC fp16 transpose of x.
// ---------------------------------------------------------------------------
__global__ void transpose_k(const float* __restrict__ x) {
    __shared__ float tile[32][33];
    int w0 = blockIdx.x * 32;
    int c0 = blockIdx.y * 32;
    int bh = blockIdx.z;
    int b  = bh >> 7;          // H = 128
    int h  = bh & 127;
    int tx = threadIdx.x, ty = threadIdx.y;
#pragma unroll
    for (int i = 0; i < 4; i++) {
        int c = c0 + ty + i * 8;
        tile[ty + i * 8][tx] = x[((b * Cc + c) * Hh + h) * Ww + w0 + tx];
    }
    __syncthreads();
#pragma unroll
    for (int i = 0; i < 4; i++) {
        int w = w0 + ty + i * 8;
        g_xT[((size_t)(b * Hh + h) * Ww + w) * Cc + c0 + tx] =
            __float2half_rn(tile[tx][ty + i * 8]);
    }
}

// ---------------------------------------------------------------------------
// Kernel 2: pure streaming bilinear gather. One 8-lane group per point.
// grid: (NPT/32, Bsz), block 256. No smem, no barriers, no shuffles.
// ---------------------------------------------------------------------------
__global__ __launch_bounds__(256) void gather_k(const float* __restrict__ grid) {
    const int t    = threadIdx.x;
    const int b    = blockIdx.y;
    const int p    = blockIdx.x * 32 + (t >> 3);   // global point index
    const int lane = t & 7;
    const int co   = lane * 8;                     // channel offset (halves)
    const __half* __restrict__ xc = g_xT + (size_t)b * (Hh * Ww * Cc) + co;

    // Broadcast grid load (all 8 lanes of a group read the same 8B)
    float2 g2 = __ldg((const float2*)grid + p);
    float gx = (g2.x + 1.0f) * 128.0f - 0.5f;   // W/2
    float gy = (g2.y + 1.0f) * 64.0f  - 0.5f;   // H/2
    float x0f = floorf(gx), y0f = floorf(gy);
    float wx = gx - x0f, wy = gy - y0f;
    int x0 = (int)x0f, y0 = (int)y0f;
    float vx0 = ((unsigned)x0       < (unsigned)Ww) ? 1.f : 0.f;
    float vx1 = ((unsigned)(x0 + 1) < (unsigned)Ww) ? 1.f : 0.f;
    float vy0 = ((unsigned)y0       < (unsigned)Hh) ? 1.f : 0.f;
    float vy1 = ((unsigned)(y0 + 1) < (unsigned)Hh) ? 1.f : 0.f;
    float w00 = (1.f - wx) * (1.f - wy) * vx0 * vy0;
    float w10 = wx * (1.f - wy)         * vx1 * vy0;
    float w01 = (1.f - wx) * wy         * vx0 * vy1;
    float w11 = wx * wy                 * vx1 * vy1;
    int xc0 = min(max(x0, 0), Ww - 1);
    int xc1 = min(max(x0 + 1, 0), Ww - 1);
    int yc0 = min(max(y0, 0), Hh - 1);
    int yc1 = min(max(y0 + 1, 0), Hh - 1);

    // 4 unconditional 16B taps
    uint4 u0 = *(const uint4*)(xc + (yc0 * Ww + xc0) * 64);
    uint4 u1 = *(const uint4*)(xc + (yc0 * Ww + xc1) * 64);
    uint4 u2 = *(const uint4*)(xc + (yc1 * Ww + xc0) * 64);
    uint4 u3 = *(const uint4*)(xc + (yc1 * Ww + xc1) * 64);

    float acc[8];
#pragma unroll
    for (int k = 0; k < 8; k++) acc[k] = 0.f;
    const uint4* us[4] = { &u0, &u1, &u2, &u3 };
    const float  ws[4] = { w00, w10, w01, w11 };
#pragma unroll
    for (int tap = 0; tap < 4; tap++) {
        uint4 u = *us[tap];
        float w = ws[tap];
        float2 f0 = __half22float2(*(__half2*)&u.x);
        float2 f1 = __half22float2(*(__half2*)&u.y);
        float2 f2 = __half22float2(*(__half2*)&u.z);
        float2 f3 = __half22float2(*(__half2*)&u.w);
        acc[0] = fmaf(w, f0.x, acc[0]); acc[1] = fmaf(w, f0.y, acc[1]);
        acc[2] = fmaf(w, f1.x, acc[2]); acc[3] = fmaf(w, f1.y, acc[3]);
        acc[4] = fmaf(w, f2.x, acc[4]); acc[5] = fmaf(w, f2.y, acc[5]);
        acc[6] = fmaf(w, f3.x, acc[6]); acc[7] = fmaf(w, f3.y, acc[7]);
    }
    __half2 hv[4];
#pragma unroll
    for (int k = 0; k < 4; k++)
        hv[k] = __floats2half2_rn(acc[2*k], acc[2*k+1]);
    // Contiguous 512B per warp (4 consecutive points x 128B)
    *(uint4*)&g_v[((size_t)b * NPT + p) * 64 + co] = *(uint4*)hv;
}

// ---------------------------------------------------------------------------
// Kernel 3: spatial attention + depthwise(s=3) from g_v -> g_z (fp16)
// grid: (LOUT/TL, B), block 256.
// ---------------------------------------------------------------------------
__global__ __launch_bounds__(256) void dwattn_k(
    const float* __restrict__ sa_w, const float* __restrict__ sa_b,
    const float* __restrict__ dw_w, const float* __restrict__ dw_b)
{
    __shared__ __align__(16) __half2 v_sm2[NP * VROW]; // 21600 B sampled vecs
    __shared__ float savg[NP];
    __shared__ float smax_[NP];
    __shared__ float m_att[TL * 3 * 3];                // (1 + sigmoid) gates
    __shared__ float dw_sm[64 * 9];

    const int t  = threadIdx.x;
    const int b  = blockIdx.y;
    const int l0 = blockIdx.x * TL;

    // ---- Stage 0: dw weights + stream the 150-point window from g_v --------
    for (int i = t; i < 576; i += 256)
        dw_sm[i] = dw_w[i];

    {
        const int lane = t & 7;
        const int co   = lane * 8;                   // halves
        const int gbase = (3 * l0 - 1) * 3;          // global point of local 0
        for (int p = t >> 3; p < NP; p += 32) {
            int gp = gbase + p;
            uint4 u = make_uint4(0u, 0u, 0u, 0u);
            if (gp >= 0 && gp < NPT)
                u = *(const uint4*)&g_v[((size_t)b * NPT + gp) * 64 + co];
            *(uint4*)&v_sm2[p * VROW + lane * 4] = u;
        }
    }
    __syncthreads();

    // ---- Stage 1: per-point channel avg / max (1 thread per point) ---------
    if (t < NP) {
        const __half2* row = &v_sm2[t * VROW];
        float sum = 0.f, mx = -3.0e38f;
#pragma unroll
        for (int k = 0; k < 8; k++) {
            uint4 u = *(const uint4*)(row + k * 4);
            float2 f0 = __half22float2(*(__half2*)&u.x);
            float2 f1 = __half22float2(*(__half2*)&u.y);
            float2 f2 = __half22float2(*(__half2*)&u.z);
            float2 f3 = __half22float2(*(__half2*)&u.w);
            sum += (f0.x + f0.y) + (f1.x + f1.y) + (f2.x + f2.y) + (f3.x + f3.y);
            mx = fmaxf(mx, fmaxf(fmaxf(f0.x, f0.y), fmaxf(f1.x, f1.y)));
            mx = fmaxf(mx, fmaxf(fmaxf(f2.x, f2.y), fmaxf(f3.x, f3.y)));
        }
        savg[t] = sum * (1.0f / 64.0f);
        smax_[t] = mx;
    }
    __syncthreads();

    // ---- Stage 2: spatial attention gates ----------------------------------
    if (t < TL * 3 * 3) {
        int ra = t / 3, kw = t - ra * 3;   // interior row ra -> v-row ra+1
        float acc = __ldg(sa_b);
#pragma unroll
        for (int kh = 0; kh < 3; kh++) {
            int rr = ra + kh;
#pragma unroll
            for (int k2 = 0; k2 < 3; k2++) {
                int cc = kw + k2 - 1;
                if (cc >= 0 && cc < 3) {
                    int p = rr * 3 + cc;
                    acc += __ldg(&sa_w[kh * 3 + k2])     * savg[p]
                         + __ldg(&sa_w[9 + kh * 3 + k2]) * smax_[p];
                }
            }
        }
        m_att[t] = 1.0f + 1.0f / (1.0f + __expf(-acc));
    }
    __syncthreads();

    // ---- Stage 3: depthwise 3x3 -> g_z (fp16, coalesced) -------------------
    {
        int c2 = t & 31;           // half2 channel pair (2 channels)
        int lg = t >> 5;           // 0..7
        int cA = 2 * c2, cB = 2 * c2 + 1;
        float dwA[9], dwB[9];
#pragma unroll
        for (int k = 0; k < 9; k++) { dwA[k] = dw_sm[cA * 9 + k]; dwB[k] = dw_sm[cB * 9 + k]; }
        float dbA = __ldg(&dw_b[cA]), dbB = __ldg(&dw_b[cB]);
#pragma unroll
        for (int li = 0; li < 2; li++) {
            int l = lg + li * 8;
            float a0 = dbA, a1 = dbB;
#pragma unroll
            for (int kh = 0; kh < 3; kh++)
#pragma unroll
                for (int kw = 0; kw < 3; kw++) {
                    int ra = 3 * l + kh;
                    float g = m_att[ra * 3 + kw];
                    float2 v = __half22float2(v_sm2[((ra + 1) * 3 + kw) * VROW + c2]);
                    a0 = fmaf(dwA[kh * 3 + kw] * g, v.x, a0);
                    a1 = fmaf(dwB[kh * 3 + kw] * g, v.y, a1);
                }
            *(__half2*)&g_z[((size_t)b * LOUT + l0 + l) * 64 + cA] =
                __floats2half2_rn(a0, a1);
        }
    }
}

// ---------------------------------------------------------------------------
// Kernel 4: pointwise 64x64 GEMM: out[b,o,l] = sum_c pw[o,c] * z[b,l,c] + pb.
// grid: (Bsz*LOUT/64), block 256. Tile 64o x 64l, thread 4o x 4l, k-major smem.
// ---------------------------------------------------------------------------
__global__ __launch_bounds__(256) void pw_k(
    const float* __restrict__ pw_w, const float* __restrict__ pw_b,
    float* __restrict__ out)
{
    __shared__ __align__(16) float zs[64][68];   // [c][l]
    __shared__ __align__(16) float pws[64][68];  // [c][o]

    const int t   = threadIdx.x;
    const int bl0 = blockIdx.x * 64;             // flattened (b*LOUT + l) tile base
    const int b   = bl0 / LOUT;                  // tiles never cross batch
    const int lbase = bl0 - b * LOUT;

    // Load pw transposed to [c][o]
    for (int i = t * 4; i < 4096; i += 1024) {
        float4 v = *(const float4*)&pw_w[i];
        int o = i >> 6, c = i & 63;
        pws[c + 0][o] = v.x; pws[c + 1][o] = v.y;
        pws[c + 2][o] = v.z; pws[c + 3][o] = v.w;
    }
    // Load z tile (fp16) transposed to [c][l] as fp32
    const __half* zg = g_z + (size_t)bl0 * 64;
    for (int i = t * 8; i < 4096; i += 2048) {
        uint4 u = *(const uint4*)&zg[i];       // 8 halves
        int l = i >> 6, c = i & 63;
        float2 f0 = __half22float2(*(__half2*)&u.x);
        float2 f1 = __half22float2(*(__half2*)&u.y);
        float2 f2 = __half22float2(*(__half2*)&u.z);
        float2 f3 = __half22float2(*(__half2*)&u.w);
        zs[c + 0][l] = f0.x; zs[c + 1][l] = f0.y;
        zs[c + 2][l] = f1.x; zs[c + 3][l] = f1.y;
        zs[c + 4][l] = f2.x; zs[c + 5][l] = f2.y;
        zs[c + 6][l] = f3.x; zs[c + 7][l] = f3.y;
    }
    __syncthreads();

    const int tx = t & 15, ty = t >> 4;
    const int o0 = tx * 4, lt = ty * 4;

    float acc[4][4];
#pragma unroll
    for (int i = 0; i < 4; i++) {
        float pb = __ldg(&pw_b[o0 + i]);
#pragma unroll
        for (int j = 0; j < 4; j++) acc[i][j] = pb;
    }

#pragma unroll 8
    for (int k = 0; k < 64; k++) {
        float4 a  = *(const float4*)&pws[k][o0];
        float4 zv = *(const float4*)&zs[k][lt];
        acc[0][0] = fmaf(a.x, zv.x, acc[0][0]); acc[0][1] = fmaf(a.x, zv.y, acc[0][1]);
        acc[0][2] = fmaf(a.x, zv.z, acc[0][2]); acc[0][3] = fmaf(a.x, zv.w, acc[0][3]);
        acc[1][0] = fmaf(a.y, zv.x, acc[1][0]); acc[1][1] = fmaf(a.y, zv.y, acc[1][1]);
        acc[1][2] = fmaf(a.y, zv.z, acc[1][2]); acc[1][3] = fmaf(a.y, zv.w, acc[1][3]);
        acc[2][0] = fmaf(a.z, zv.x, acc[2][0]); acc[2][1] = fmaf(a.z, zv.y, acc[2][1]);
        acc[2][2] = fmaf(a.z, zv.z, acc[2][2]); acc[2][3] = fmaf(a.z, zv.w, acc[2][3]);
        acc[3][0] = fmaf(a.w, zv.x, acc[3][0]); acc[3][1] = fmaf(a.w, zv.y, acc[3][1]);
        acc[3][2] = fmaf(a.w, zv.z, acc[3][2]); acc[3][3] = fmaf(a.w, zv.w, acc[3][3]);
    }

#pragma unroll
    for (int i = 0; i < 4; i++) {
        float4 r = make_float4(acc[i][0], acc[i][1], acc[i][2], acc[i][3]);
        *(float4*)&out[((size_t)(b * 64 + o0 + i)) * LOUT + lbase + lt] = r;
    }
}

// ---------------------------------------------------------------------------
extern "C" void kernel_launch(void* const* d_in, const int* in_sizes, int n_in,
                              void* d_out, int out_size) {
    (void)in_sizes; (void)n_in; (void)out_size;
    const float* x    = (const float*)d_in[0];
    const float* grid = (const float*)d_in[1];
    const float* sa_w = (const float*)d_in[2];
    const float* sa_b = (const float*)d_in[3];
    const float* dw_w = (const float*)d_in[4];
    const float* dw_b = (const float*)d_in[5];
    const float* pw_w = (const float*)d_in[6];
    const float* pw_b = (const float*)d_in[7];
    float* out = (float*)d_out;

    dim3 tb(32, 8);
    dim3 tg(Ww / 32, Cc / 32, Bsz * Hh);
    transpose_k<<<tg, tb>>>(x);

    dim3 gg(NPT / 32, Bsz);
    gather_k<<<gg, 256>>>(grid);

    dim3 dg(LOUT / TL, Bsz);
    dwattn_k<<<dg, 256>>>(sa_w, sa_b, dw_w, dw_b);

    pw_k<<<(Bsz * LOUT) / 64, 256>>>(pw_w, pw_b, out);
}

// round 13
// speedup vs baseline: 1.2923x; 1.2923x over previous
#include <cuda_runtime.h>
#include <cuda_fp16.h>

// Problem constants
#define Bsz  2
#define Cc   64
#define Hh   128
#define Ww   256
#define HG   122880          // grid rows = L*KH
#define LOUT 40960           // output rows after stride-3 depthwise
#define TL   16              // output rows per block (sampler)
#define NR   (3*TL + 2)      // local sampled rows incl. +/-1 halo  (50)
#define NP   (NR * 3)        // local sampled points (150)
#define VROW 36              // v_sm2 row pitch in half2 (144B)
#define LTI  256             // pw_k l-tile

__device__ __half g_xT[Bsz * Hh * Ww * Cc];        // x as [B,H,W,C] fp16
__device__ __half g_z[Bsz * LOUT * Cc];            // depthwise output [b*l][c] fp16

// ---------------------------------------------------------------------------
// Kernel 1: NCHW fp32 -> NHWC fp16 transpose of x.
// ---------------------------------------------------------------------------
__global__ void transpose_k(const float* __restrict__ x) {
    __shared__ float tile[32][33];
    int w0 = blockIdx.x * 32;
    int c0 = blockIdx.y * 32;
    int bh = blockIdx.z;
    int b  = bh >> 7;          // H = 128
    int h  = bh & 127;
    int tx = threadIdx.x, ty = threadIdx.y;
#pragma unroll
    for (int i = 0; i < 4; i++) {
        int c = c0 + ty + i * 8;
        tile[ty + i * 8][tx] = x[((b * Cc + c) * Hh + h) * Ww + w0 + tx];
    }
    __syncthreads();
#pragma unroll
    for (int i = 0; i < 4; i++) {
        int w = w0 + ty + i * 8;
        g_xT[((size_t)(b * Hh + h) * Ww + w) * Cc + c0 + tx] =
            __float2half_rn(tile[tx][ty + i * 8]);
    }
}

// ---------------------------------------------------------------------------
// Kernel 2: grid_sample + spatial attention + depthwise(s=3) -> g_z (fp16)
// grid: (LOUT/TL, B), block 256. Branch-free clamped gather. (R11 version)
// ---------------------------------------------------------------------------
__global__ __launch_bounds__(256) void sample_k(
    const float* __restrict__ grid,
    const float* __restrict__ sa_w, const float* __restrict__ sa_b,
    const float* __restrict__ dw_w, const float* __restrict__ dw_b)
{
    __shared__ __align__(16) __half2 v_sm2[NP * VROW]; // 21600 B sampled vecs
    __shared__ __align__(16) float4 cw_sm[NP];         // per-tap weights (0 if OOB)
    __shared__ unsigned cxy_sm[NP];                    // packed clamped coords
    __shared__ float savg[NP];
    __shared__ float smax_[NP];
    __shared__ float m_att[TL * 3 * 3];                // (1 + sigmoid) gates
    __shared__ float dw_sm[64 * 9];

    const int t  = threadIdx.x;
    const int b  = blockIdx.y;
    const int l0 = blockIdx.x * TL;
    const __half* __restrict__ xb = g_xT + (size_t)b * (Hh * Ww * Cc);

    // ---- Stage 0: dw weights + per-point coordinate precompute -------------
    for (int i = t; i < 576; i += 256)
        dw_sm[i] = dw_w[i];

    if (t < NP) {
        float4 w4 = make_float4(0.f, 0.f, 0.f, 0.f);
        int xc0 = 0, xc1 = 0, yc0 = 0, yc1 = 0;
        int gidx = (3 * l0 - 1) * 3 + t;              // linear grid point index
        if (gidx >= 0 && gidx < HG * 3) {
            float2 g2 = __ldg((const float2*)grid + gidx);
            float gx = (g2.x + 1.0f) * 128.0f - 0.5f;   // W/2
            float gy = (g2.y + 1.0f) * 64.0f  - 0.5f;   // H/2
            float x0f = floorf(gx), y0f = floorf(gy);
            float wx = gx - x0f, wy = gy - y0f;
            int x0 = (int)x0f, y0 = (int)y0f;
            float vx0 = ((unsigned)x0       < (unsigned)Ww) ? 1.f : 0.f;
            float vx1 = ((unsigned)(x0 + 1) < (unsigned)Ww) ? 1.f : 0.f;
            float vy0 = ((unsigned)y0       < (unsigned)Hh) ? 1.f : 0.f;
            float vy1 = ((unsigned)(y0 + 1) < (unsigned)Hh) ? 1.f : 0.f;
            w4.x = (1.f - wx) * (1.f - wy) * vx0 * vy0;  // w00
            w4.y = wx * (1.f - wy)         * vx1 * vy0;  // w10
            w4.z = (1.f - wx) * wy         * vx0 * vy1;  // w01
            w4.w = wx * wy                 * vx1 * vy1;  // w11
            xc0 = min(max(x0, 0), Ww - 1);
            xc1 = min(max(x0 + 1, 0), Ww - 1);
            yc0 = min(max(y0, 0), Hh - 1);
            yc1 = min(max(y0 + 1, 0), Hh - 1);
        }
        cw_sm[t] = w4;
        cxy_sm[t] = (unsigned)xc0 | ((unsigned)xc1 << 8)
                  | ((unsigned)yc0 << 16) | ((unsigned)yc1 << 24);
    }
    __syncthreads();

    // ---- Stage 1: branch-free bilinear gather, 8 lanes/pt, 8 ch/lane -------
    const int grp  = t >> 3;      // 0..31
    const int lane = t & 7;
    const int co   = lane * 8;    // channel offset (halves)
    const __half* __restrict__ xc = xb + co;

    for (int p = grp; p < NP; p += 32) {
        float4 w4 = cw_sm[p];
        unsigned pk = cxy_sm[p];
        int xc0 = pk & 255, xc1 = (pk >> 8) & 255;
        int yc0 = (pk >> 16) & 255, yc1 = pk >> 24;
        uint4 u0 = *(const uint4*)(xc + (yc0 * Ww + xc0) * 64);
        uint4 u1 = *(const uint4*)(xc + (yc0 * Ww + xc1) * 64);
        uint4 u2 = *(const uint4*)(xc + (yc1 * Ww + xc0) * 64);
        uint4 u3 = *(const uint4*)(xc + (yc1 * Ww + xc1) * 64);

        float acc[8];
#pragma unroll
        for (int k = 0; k < 8; k++) acc[k] = 0.f;
        const uint4* us[4] = { &u0, &u1, &u2, &u3 };
        const float  ws[4] = { w4.x, w4.y, w4.z, w4.w };
#pragma unroll
        for (int tap = 0; tap < 4; tap++) {
            uint4 u = *us[tap];
            float w = ws[tap];
            float2 f0 = __half22float2(*(__half2*)&u.x);
            float2 f1 = __half22float2(*(__half2*)&u.y);
            float2 f2 = __half22float2(*(__half2*)&u.z);
            float2 f3 = __half22float2(*(__half2*)&u.w);
            acc[0] = fmaf(w, f0.x, acc[0]); acc[1] = fmaf(w, f0.y, acc[1]);
            acc[2] = fmaf(w, f1.x, acc[2]); acc[3] = fmaf(w, f1.y, acc[3]);
            acc[4] = fmaf(w, f2.x, acc[4]); acc[5] = fmaf(w, f2.y, acc[5]);
            acc[6] = fmaf(w, f3.x, acc[6]); acc[7] = fmaf(w, f3.y, acc[7]);
        }
        __half2 hv[4];
#pragma unroll
        for (int k = 0; k < 4; k++)
            hv[k] = __floats2half2_rn(acc[2*k], acc[2*k+1]);
        *(uint4*)&v_sm2[p * VROW + lane * 4] = *(uint4*)hv;
    }
    __syncthreads();

    // ---- Stage 1.5: per-point channel avg / max (1 thread per point) -------
    if (t < NP) {
        const __half2* row = &v_sm2[t * VROW];
        float sum = 0.f, mx = -3.0e38f;
#pragma unroll
        for (int k = 0; k < 8; k++) {
            uint4 u = *(const uint4*)(row + k * 4);
            float2 f0 = __half22float2(*(__half2*)&u.x);
            float2 f1 = __half22float2(*(__half2*)&u.y);
            float2 f2 = __half22float2(*(__half2*)&u.z);
            float2 f3 = __half22float2(*(__half2*)&u.w);
            sum += (f0.x + f0.y) + (f1.x + f1.y) + (f2.x + f2.y) + (f3.x + f3.y);
            mx = fmaxf(mx, fmaxf(fmaxf(f0.x, f0.y), fmaxf(f1.x, f1.y)));
            mx = fmaxf(mx, fmaxf(fmaxf(f2.x, f2.y), fmaxf(f3.x, f3.y)));
        }
        savg[t] = sum * (1.0f / 64.0f);
        smax_[t] = mx;
    }
    __syncthreads();

    // ---- Stage 2: spatial attention gates ----------------------------------
    if (t < TL * 3 * 3) {
        int ra = t / 3, kw = t - ra * 3;   // interior row ra -> v-row ra+1
        float acc = __ldg(sa_b);
#pragma unroll
        for (int kh = 0; kh < 3; kh++) {
            int rr = ra + kh;
#pragma unroll
            for (int k2 = 0; k2 < 3; k2++) {
                int cc = kw + k2 - 1;
                if (cc >= 0 && cc < 3) {
                    int p = rr * 3 + cc;
                    acc += __ldg(&sa_w[kh * 3 + k2])     * savg[p]
                         + __ldg(&sa_w[9 + kh * 3 + k2]) * smax_[p];
                }
            }
        }
        m_att[t] = 1.0f + 1.0f / (1.0f + __expf(-acc));
    }
    __syncthreads();

    // ---- Stage 3: depthwise 3x3 -> g_z (fp16, coalesced) -------------------
    {
        int c2 = t & 31;           // half2 channel pair (2 channels)
        int lg = t >> 5;           // 0..7
        int cA = 2 * c2, cB = 2 * c2 + 1;
        float dwA[9], dwB[9];
#pragma unroll
        for (int k = 0; k < 9; k++) { dwA[k] = dw_sm[cA * 9 + k]; dwB[k] = dw_sm[cB * 9 + k]; }
        float dbA = __ldg(&dw_b[cA]), dbB = __ldg(&dw_b[cB]);
#pragma unroll
        for (int li = 0; li < 2; li++) {
            int l = lg + li * 8;
            float a0 = dbA, a1 = dbB;
#pragma unroll
            for (int kh = 0; kh < 3; kh++)
#pragma unroll
                for (int kw = 0; kw < 3; kw++) {
                    int ra = 3 * l + kh;
                    float g = m_att[ra * 3 + kw];
                    float2 v = __half22float2(v_sm2[((ra + 1) * 3 + kw) * VROW + c2]);
                    a0 = fmaf(dwA[kh * 3 + kw] * g, v.x, a0);
                    a1 = fmaf(dwB[kh * 3 + kw] * g, v.y, a1);
                }
            *(__half2*)&g_z[((size_t)b * LOUT + l0 + l) * 64 + cA] =
                __floats2half2_rn(a0, a1);
        }
    }
}

// ---------------------------------------------------------------------------
// Kernel 3: pointwise 64x64 GEMM, fp16 operands / fp32 accumulate.
// Tile 64o x 256l per block, thread tile 8o x 8l (half2 c-pairs).
// grid: (Bsz*LOUT/LTI), block 256.
// ---------------------------------------------------------------------------
__global__ __launch_bounds__(256) void pw_k(
    const float* __restrict__ pw_w, const float* __restrict__ pw_b,
    float* __restrict__ out)
{
    __shared__ __align__(16) __half2 pws2[32][68];   // [c2][o]  (c-pair per elem)
    __shared__ __align__(16) __half2 zs2[32][264];   // [c2][l]

    const int t   = threadIdx.x;
    const int bl0 = blockIdx.x * LTI;
    const int b   = bl0 / LOUT;
    const int lbase = bl0 - b * LOUT;

    // Stage pw: fp32 [o][c] -> half2 [c2][o]
    {
        int o = t & 63, c2b = t >> 6;    // c2b 0..3
#pragma unroll
        for (int j = 0; j < 8; j++) {
            int c2 = c2b + j * 4;
            float2 f = *(const float2*)&pw_w[o * 64 + c2 * 2];
            pws2[c2][o] = __floats2half2_rn(f.x, f.y);
        }
    }
    // Stage z: fp16 [l][c] -> half2 [c2][l] (warp-linear, conflict-free)
    {
        const __half* zg = g_z + (size_t)bl0 * 64;
        int c8 = (t >> 5) * 8, c2b = (t >> 5) * 4, lt = t & 31;
#pragma unroll
        for (int j = 0; j < 8; j++) {
            int l = j * 32 + lt;
            uint4 u = *(const uint4*)&zg[l * 64 + c8];
            zs2[c2b + 0][l] = *(__half2*)&u.x;
            zs2[c2b + 1][l] = *(__half2*)&u.y;
            zs2[c2b + 2][l] = *(__half2*)&u.z;
            zs2[c2b + 3][l] = *(__half2*)&u.w;
        }
    }
    __syncthreads();

    const int o0 = (t & 7) * 8, l0 = (t >> 3) * 8;
    float acc[8][8];
#pragma unroll
    for (int i = 0; i < 8; i++) {
        float pb = __ldg(&pw_b[o0 + i]);
#pragma unroll
        for (int j = 0; j < 8; j++) acc[i][j] = pb;
    }

#pragma unroll 4
    for (int k2 = 0; k2 < 32; k2++) {
        __half2 po[8], zl[8];
        *(uint4*)&po[0] = *(const uint4*)&pws2[k2][o0];
        *(uint4*)&po[4] = *(const uint4*)&pws2[k2][o0 + 4];
        *(uint4*)&zl[0] = *(const uint4*)&zs2[k2][l0];
        *(uint4*)&zl[4] = *(const uint4*)&zs2[k2][l0 + 4];
        float2 fo[8], fl[8];
#pragma unroll
        for (int i = 0; i < 8; i++) {
            fo[i] = __half22float2(po[i]);
            fl[i] = __half22float2(zl[i]);
        }
#pragma unroll
        for (int i = 0; i < 8; i++)
#pragma unroll
            for (int j = 0; j < 8; j++) {
                acc[i][j] = fmaf(fo[i].x, fl[j].x, acc[i][j]);
                acc[i][j] = fmaf(fo[i].y, fl[j].y, acc[i][j]);
            }
    }

#pragma unroll
    for (int i = 0; i < 8; i++) {
        size_t base = ((size_t)(b * 64 + o0 + i)) * LOUT + lbase + l0;
        *(float4*)&out[base]     = make_float4(acc[i][0], acc[i][1], acc[i][2], acc[i][3]);
        *(float4*)&out[base + 4] = make_float4(acc[i][4], acc[i][5], acc[i][6], acc[i][7]);
    }
}

// ---------------------------------------------------------------------------
extern "C" void kernel_launch(void* const* d_in, const int* in_sizes, int n_in,
                              void* d_out, int out_size) {
    (void)in_sizes; (void)n_in; (void)out_size;
    const float* x    = (const float*)d_in[0];
    const float* grid = (const float*)d_in[1];
    const float* sa_w = (const float*)d_in[2];
    const float* sa_b = (const float*)d_in[3];
    const float* dw_w = (const float*)d_in[4];
    const float* dw_b = (const float*)d_in[5];
    const float* pw_w = (const float*)d_in[6];
    const float* pw_b = (const float*)d_in[7];
    float* out = (float*)d_out;

    dim3 tb(32, 8);
    dim3 tg(Ww / 32, Cc / 32, Bsz * Hh);
    transpose_k<<<tg, tb>>>(x);

    dim3 sg(LOUT / TL, Bsz);
    sample_k<<<sg, 256>>>(grid, sa_w, sa_b, dw_w, dw_b);

    pw_k<<<(Bsz * LOUT) / LTI, 256>>>(pw_w, pw_b, out);
}

// round 14
// speedup vs baseline: 1.7760x; 1.3743x over previous
#include <cuda_runtime.h>
#include <cuda_fp16.h>
#include <mma.h>
using namespace nvcuda;

// Problem constants
#define Bsz  2
#define Cc   64
#define Hh   128
#define Ww   256
#define HG   122880          // grid rows = L*KH
#define LOUT 40960           // output rows after stride-3 depthwise
#define TL   16              // output rows per block (sampler)
#define NR   (3*TL + 2)      // local sampled rows incl. +/-1 halo  (50)
#define NP   (NR * 3)        // local sampled points (150)
#define VROW 36              // v_sm2 row pitch in half2 (144B)
#define LTI  128             // pw_k l-tile

__device__ __half g_xT[Bsz * Hh * Ww * Cc];        // x as [B,H,W,C] fp16
__device__ __half g_z[Bsz * LOUT * Cc];            // depthwise output [b*l][c] fp16

// ---------------------------------------------------------------------------
// Kernel 1: NCHW fp32 -> NHWC fp16 transpose of x.
// ---------------------------------------------------------------------------
__global__ void transpose_k(const float* __restrict__ x) {
    __shared__ float tile[32][33];
    int w0 = blockIdx.x * 32;
    int c0 = blockIdx.y * 32;
    int bh = blockIdx.z;
    int b  = bh >> 7;          // H = 128
    int h  = bh & 127;
    int tx = threadIdx.x, ty = threadIdx.y;
#pragma unroll
    for (int i = 0; i < 4; i++) {
        int c = c0 + ty + i * 8;
        tile[ty + i * 8][tx] = x[((b * Cc + c) * Hh + h) * Ww + w0 + tx];
    }
    __syncthreads();
#pragma unroll
    for (int i = 0; i < 4; i++) {
        int w = w0 + ty + i * 8;
        g_xT[((size_t)(b * Hh + h) * Ww + w) * Cc + c0 + tx] =
            __float2half_rn(tile[tx][ty + i * 8]);
    }
}

// ---------------------------------------------------------------------------
// Kernel 2: grid_sample + spatial attention + depthwise(s=3) -> g_z (fp16)
// grid: (LOUT/TL, B), block 256. Branch-free clamped gather. (R11 version)
// ---------------------------------------------------------------------------
__global__ __launch_bounds__(256) void sample_k(
    const float* __restrict__ grid,
    const float* __restrict__ sa_w, const float* __restrict__ sa_b,
    const float* __restrict__ dw_w, const float* __restrict__ dw_b)
{
    __shared__ __align__(16) __half2 v_sm2[NP * VROW]; // 21600 B sampled vecs
    __shared__ __align__(16) float4 cw_sm[NP];         // per-tap weights (0 if OOB)
    __shared__ unsigned cxy_sm[NP];                    // packed clamped coords
    __shared__ float savg[NP];
    __shared__ float smax_[NP];
    __shared__ float m_att[TL * 3 * 3];                // (1 + sigmoid) gates
    __shared__ float dw_sm[64 * 9];

    const int t  = threadIdx.x;
    const int b  = blockIdx.y;
    const int l0 = blockIdx.x * TL;
    const __half* __restrict__ xb = g_xT + (size_t)b * (Hh * Ww * Cc);

    // ---- Stage 0: dw weights + per-point coordinate precompute -------------
    for (int i = t; i < 576; i += 256)
        dw_sm[i] = dw_w[i];

    if (t < NP) {
        float4 w4 = make_float4(0.f, 0.f, 0.f, 0.f);
        int xc0 = 0, xc1 = 0, yc0 = 0, yc1 = 0;
        int gidx = (3 * l0 - 1) * 3 + t;              // linear grid point index
        if (gidx >= 0 && gidx < HG * 3) {
            float2 g2 = __ldg((const float2*)grid + gidx);
            float gx = (g2.x + 1.0f) * 128.0f - 0.5f;   // W/2
            float gy = (g2.y + 1.0f) * 64.0f  - 0.5f;   // H/2
            float x0f = floorf(gx), y0f = floorf(gy);
            float wx = gx - x0f, wy = gy - y0f;
            int x0 = (int)x0f, y0 = (int)y0f;
            float vx0 = ((unsigned)x0       < (unsigned)Ww) ? 1.f : 0.f;
            float vx1 = ((unsigned)(x0 + 1) < (unsigned)Ww) ? 1.f : 0.f;
            float vy0 = ((unsigned)y0       < (unsigned)Hh) ? 1.f : 0.f;
            float vy1 = ((unsigned)(y0 + 1) < (unsigned)Hh) ? 1.f : 0.f;
            w4.x = (1.f - wx) * (1.f - wy) * vx0 * vy0;  // w00
            w4.y = wx * (1.f - wy)         * vx1 * vy0;  // w10
            w4.z = (1.f - wx) * wy         * vx0 * vy1;  // w01
            w4.w = wx * wy                 * vx1 * vy1;  // w11
            xc0 = min(max(x0, 0), Ww - 1);
            xc1 = min(max(x0 + 1, 0), Ww - 1);
            yc0 = min(max(y0, 0), Hh - 1);
            yc1 = min(max(y0 + 1, 0), Hh - 1);
        }
        cw_sm[t] = w4;
        cxy_sm[t] = (unsigned)xc0 | ((unsigned)xc1 << 8)
                  | ((unsigned)yc0 << 16) | ((unsigned)yc1 << 24);
    }
    __syncthreads();

    // ---- Stage 1: branch-free bilinear gather, 8 lanes/pt, 8 ch/lane -------
    const int grp  = t >> 3;      // 0..31
    const int lane = t & 7;
    const int co   = lane * 8;    // channel offset (halves)
    const __half* __restrict__ xc = xb + co;

    for (int p = grp; p < NP; p += 32) {
        float4 w4 = cw_sm[p];
        unsigned pk = cxy_sm[p];
        int xc0 = pk & 255, xc1 = (pk >> 8) & 255;
        int yc0 = (pk >> 16) & 255, yc1 = pk >> 24;
        uint4 u0 = *(const uint4*)(xc + (yc0 * Ww + xc0) * 64);
        uint4 u1 = *(const uint4*)(xc + (yc0 * Ww + xc1) * 64);
        uint4 u2 = *(const uint4*)(xc + (yc1 * Ww + xc0) * 64);
        uint4 u3 = *(const uint4*)(xc + (yc1 * Ww + xc1) * 64);

        float acc[8];
#pragma unroll
        for (int k = 0; k < 8; k++) acc[k] = 0.f;
        const uint4* us[4] = { &u0, &u1, &u2, &u3 };
        const float  ws[4] = { w4.x, w4.y, w4.z, w4.w };
#pragma unroll
        for (int tap = 0; tap < 4; tap++) {
            uint4 u = *us[tap];
            float w = ws[tap];
            float2 f0 = __half22float2(*(__half2*)&u.x);
            float2 f1 = __half22float2(*(__half2*)&u.y);
            float2 f2 = __half22float2(*(__half2*)&u.z);
            float2 f3 = __half22float2(*(__half2*)&u.w);
            acc[0] = fmaf(w, f0.x, acc[0]); acc[1] = fmaf(w, f0.y, acc[1]);
            acc[2] = fmaf(w, f1.x, acc[2]); acc[3] = fmaf(w, f1.y, acc[3]);
            acc[4] = fmaf(w, f2.x, acc[4]); acc[5] = fmaf(w, f2.y, acc[5]);
            acc[6] = fmaf(w, f3.x, acc[6]); acc[7] = fmaf(w, f3.y, acc[7]);
        }
        __half2 hv[4];
#pragma unroll
        for (int k = 0; k < 4; k++)
            hv[k] = __floats2half2_rn(acc[2*k], acc[2*k+1]);
        *(uint4*)&v_sm2[p * VROW + lane * 4] = *(uint4*)hv;
    }
    __syncthreads();

    // ---- Stage 1.5: per-point channel avg / max (1 thread per point) -------
    if (t < NP) {
        const __half2* row = &v_sm2[t * VROW];
        float sum = 0.f, mx = -3.0e38f;
#pragma unroll
        for (int k = 0; k < 8; k++) {
            uint4 u = *(const uint4*)(row + k * 4);
            float2 f0 = __half22float2(*(__half2*)&u.x);
            float2 f1 = __half22float2(*(__half2*)&u.y);
            float2 f2 = __half22float2(*(__half2*)&u.z);
            float2 f3 = __half22float2(*(__half2*)&u.w);
            sum += (f0.x + f0.y) + (f1.x + f1.y) + (f2.x + f2.y) + (f3.x + f3.y);
            mx = fmaxf(mx, fmaxf(fmaxf(f0.x, f0.y), fmaxf(f1.x, f1.y)));
            mx = fmaxf(mx, fmaxf(fmaxf(f2.x, f2.y), fmaxf(f3.x, f3.y)));
        }
        savg[t] = sum * (1.0f / 64.0f);
        smax_[t] = mx;
    }
    __syncthreads();

    // ---- Stage 2: spatial attention gates ----------------------------------
    if (t < TL * 3 * 3) {
        int ra = t / 3, kw = t - ra * 3;   // interior row ra -> v-row ra+1
        float acc = __ldg(sa_b);
#pragma unroll
        for (int kh = 0; kh < 3; kh++) {
            int rr = ra + kh;
#pragma unroll
            for (int k2 = 0; k2 < 3; k2++) {
                int cc = kw + k2 - 1;
                if (cc >= 0 && cc < 3) {
                    int p = rr * 3 + cc;
                    acc += __ldg(&sa_w[kh * 3 + k2])     * savg[p]
                         + __ldg(&sa_w[9 + kh * 3 + k2]) * smax_[p];
                }
            }
        }
        m_att[t] = 1.0f + 1.0f / (1.0f + __expf(-acc));
    }
    __syncthreads();

    // ---- Stage 3: depthwise 3x3 -> g_z (fp16, coalesced) -------------------
    {
        int c2 = t & 31;           // half2 channel pair (2 channels)
        int lg = t >> 5;           // 0..7
        int cA = 2 * c2, cB = 2 * c2 + 1;
        float dwA[9], dwB[9];
#pragma unroll
        for (int k = 0; k < 9; k++) { dwA[k] = dw_sm[cA * 9 + k]; dwB[k] = dw_sm[cB * 9 + k]; }
        float dbA = __ldg(&dw_b[cA]), dbB = __ldg(&dw_b[cB]);
#pragma unroll
        for (int li = 0; li < 2; li++) {
            int l = lg + li * 8;
            float a0 = dbA, a1 = dbB;
#pragma unroll
            for (int kh = 0; kh < 3; kh++)
#pragma unroll
                for (int kw = 0; kw < 3; kw++) {
                    int ra = 3 * l + kh;
                    float g = m_att[ra * 3 + kw];
                    float2 v = __half22float2(v_sm2[((ra + 1) * 3 + kw) * VROW + c2]);
                    a0 = fmaf(dwA[kh * 3 + kw] * g, v.x, a0);
                    a1 = fmaf(dwB[kh * 3 + kw] * g, v.y, a1);
                }
            *(__half2*)&g_z[((size_t)b * LOUT + l0 + l) * 64 + cA] =
                __floats2half2_rn(a0, a1);
        }
    }
}

// ---------------------------------------------------------------------------
// Kernel 3: pointwise GEMM on tensor cores (wmma m16n16k16, fp16 in, fp32 acc)
// out[o, l] = sum_c pw[o,c] * z[l,c] + pb[o].
// Block tile: 64o x 128l. 8 warps: warp w -> m-tile (w&3), n-group (w>>2).
// grid: (Bsz*LOUT/LTI), block 256.
// ---------------------------------------------------------------------------
__global__ __launch_bounds__(256) void pw_k(
    const float* __restrict__ pw_w, const float* __restrict__ pw_b,
    float* __restrict__ out)
{
    __shared__ __align__(16) __half As[64][72];    // pw [o][c]
    __shared__ __align__(16) __half Bs[LTI][72];   // z  [l][c]
    __shared__ float biasT[64][16];                // bias rows (const per row)

    const int t   = threadIdx.x;
    const int bl0 = blockIdx.x * LTI;
    const int b   = bl0 / LOUT;
    const int lbase = bl0 - b * LOUT;

    // Stage A: pw fp32 -> fp16 [o][c]
    for (int i = t * 4; i < 4096; i += 1024) {
        float4 v = *(const float4*)&pw_w[i];
        int o = i >> 6, c = i & 63;
        __half2 h0 = __floats2half2_rn(v.x, v.y);
        __half2 h1 = __floats2half2_rn(v.z, v.w);
        uint2 u; u.x = *(unsigned*)&h0; u.y = *(unsigned*)&h1;
        *(uint2*)&As[o][c] = u;
    }
    // Stage bias tile
    if (t < 64) {
        float pb = __ldg(&pw_b[t]);
#pragma unroll
        for (int j = 0; j < 16; j++) biasT[t][j] = pb;
    }
    // Stage B: z tile [l][c] fp16 (rows 16B-aligned; pitch 144B)
    {
        const __half* zg = g_z + (size_t)bl0 * 64;
        for (int i = t * 8; i < LTI * 64; i += 2048) {
            uint4 u = *(const uint4*)&zg[i];
            int l = i >> 6, c = i & 63;
            *(uint4*)&Bs[l][c] = u;
        }
    }
    __syncthreads();

    const int wid = t >> 5;
    const int m   = (wid & 3) * 16;      // o-tile base
    const int ng  = (wid >> 2) * 64;     // n-group base (4 n-tiles of 16)

    wmma::fragment<wmma::accumulator, 16, 16, 16, float> acc[4];
#pragma unroll
    for (int j = 0; j < 4; j++)
        wmma::load_matrix_sync(acc[j], &biasT[m][0], 16, wmma::mem_row_major);

#pragma unroll
    for (int k = 0; k < 64; k += 16) {
        wmma::fragment<wmma::matrix_a, 16, 16, 16, __half, wmma::row_major> af;
        wmma::load_matrix_sync(af, &As[m][k], 72);
#pragma unroll
        for (int j = 0; j < 4; j++) {
            wmma::fragment<wmma::matrix_b, 16, 16, 16, __half, wmma::col_major> bf;
            wmma::load_matrix_sync(bf, &Bs[ng + j * 16][k], 72);
            wmma::mma_sync(acc[j], af, bf, acc[j]);
        }
    }

#pragma unroll
    for (int j = 0; j < 4; j++) {
        float* dst = &out[((size_t)(b * 64 + m)) * LOUT + lbase + ng + j * 16];
        wmma::store_matrix_sync(dst, acc[j], LOUT, wmma::mem_row_major);
    }
}

// ---------------------------------------------------------------------------
extern "C" void kernel_launch(void* const* d_in, const int* in_sizes, int n_in,
                              void* d_out, int out_size) {
    (void)in_sizes; (void)n_in; (void)out_size;
    const float* x    = (const float*)d_in[0];
    const float* grid = (const float*)d_in[1];
    const float* sa_w = (const float*)d_in[2];
    const float* sa_b = (const float*)d_in[3];
    const float* dw_w = (const float*)d_in[4];
    const float* dw_b = (const float*)d_in[5];
    const float* pw_w = (const float*)d_in[6];
    const float* pw_b = (const float*)d_in[7];
    float* out = (float*)d_out;

    dim3 tb(32, 8);
    dim3 tg(Ww / 32, Cc / 32, Bsz * Hh);
    transpose_k<<<tg, tb>>>(x);

    dim3 sg(LOUT / TL, Bsz);
    sample_k<<<sg, 256>>>(grid, sa_w, sa_b, dw_w, dw_b);

    pw_k<<<(Bsz * LOUT) / LTI, 256>>>(pw_w, pw_b, out);
}